// round 1
// baseline (speedup 1.0000x reference)
#include <cuda_runtime.h>

#define Bq 4
#define T 128
#define D 300
#define D4 75            // D / 4 (float4 count per row)

// Scratch for projected q (rows 0..511), k (512..1023), v (1024..1535)
__device__ __align__(16) float g_qkv[3 * Bq * T * D];

// ---------------------------------------------------------------------------
// Kernel 1: batched projection GEMM.
// out[r,c] = A[r,:] . W[c,:] + bias[c]   (torch nn.Linear semantics)
// rows 0..511 -> query/WQ/bQ, 512..1023 -> key/WK/bK, 1024..1535 -> value/WK/bK
// 64x64 tile, 256 threads, 4x4 microtile, fp32.
// ---------------------------------------------------------------------------
__global__ __launch_bounds__(256) void proj_kernel(
    const float* __restrict__ query, const float* __restrict__ key,
    const float* __restrict__ value,
    const float* __restrict__ WQ, const float* __restrict__ bQ,
    const float* __restrict__ WK, const float* __restrict__ bK)
{
    __shared__ float A_s[16][68];
    __shared__ float W_s[16][68];

    const int row0 = blockIdx.y * 64;
    const int col0 = blockIdx.x * 64;
    const int tid  = threadIdx.x;
    const int tx   = tid & 15;   // column micro-group
    const int ty   = tid >> 4;   // row micro-group

    const int sel = row0 >> 9;   // 0: query, 1: key, 2: value (tiles never straddle)
    const float* Ap = (sel == 0) ? query : (sel == 1 ? key : value);
    const float* Wp = (sel == 0) ? WQ : WK;
    const float* bp = (sel == 0) ? bQ : bK;
    const int arow0 = row0 & 511;

    float acc[4][4];
#pragma unroll
    for (int r = 0; r < 4; r++)
#pragma unroll
        for (int c = 0; c < 4; c++) acc[r][c] = 0.f;

    for (int k0 = 0; k0 < D; k0 += 16) {
#pragma unroll
        for (int l = tid; l < 1024; l += 256) {
            int e = l & 15;
            int x = l >> 4;
            int kk = k0 + e;
            A_s[e][x] = (kk < D) ? Ap[(arow0 + x) * D + kk] : 0.f;
            int gc = col0 + x;
            W_s[e][x] = (kk < D && gc < D) ? Wp[gc * D + kk] : 0.f;
        }
        __syncthreads();
#pragma unroll
        for (int e = 0; e < 16; e++) {
            float4 a = *(const float4*)&A_s[e][ty * 4];
            float4 w = *(const float4*)&W_s[e][tx * 4];
            float av[4] = {a.x, a.y, a.z, a.w};
            float wv[4] = {w.x, w.y, w.z, w.w};
#pragma unroll
            for (int r = 0; r < 4; r++)
#pragma unroll
                for (int c = 0; c < 4; c++) acc[r][c] += av[r] * wv[c];
        }
        __syncthreads();
    }

#pragma unroll
    for (int r = 0; r < 4; r++) {
        int gr = row0 + ty * 4 + r;
#pragma unroll
        for (int c = 0; c < 4; c++) {
            int gc = col0 + tx * 4 + c;
            if (gc < D) g_qkv[gr * D + gc] = acc[r][c] + bp[gc];
        }
    }
}

// ---------------------------------------------------------------------------
// Kernel 2: fused attention. One CTA per (b, i). 512 threads.
// SMEM: hR slab [128][300] (read ONCE from HBM), q row, scores, attn.
// ---------------------------------------------------------------------------
#define SMEM_BYTES ((T * D + 304 + 128 + 128) * 4)

__global__ __launch_bounds__(512, 1) void attn_kernel(
    const float* __restrict__ hL, const float* __restrict__ hR,
    float* __restrict__ out)
{
    extern __shared__ float smem[];
    float* hR_s     = smem;              // T*D floats
    float* q_s      = smem + T * D;      // 304 floats (300 used, 16B-aligned pad)
    float* scores_s = q_s + 304;         // 128
    float* attn_s   = scores_s + 128;    // 128

    const int tid  = threadIdx.x;
    const int lane = tid & 31;
    const int w    = tid >> 5;           // 16 warps
    const int bi   = blockIdx.x;
    const int b    = bi >> 7;
    const int i    = bi & 127;

    const float4* qkv4  = (const float4*)g_qkv;
    const float4* hR4   = (const float4*)hR;
    float4*       hR_s4 = (float4*)hR_s;
    float4*       q_s4  = (float4*)q_s;

    // ---- Phase A: stage hR[b, :, i, :] (153.6 KB) and q_i into SMEM ----
    for (int idx = tid; idx < T * D4; idx += 512) {
        int j = idx / D4;
        int c = idx - j * D4;
        hR_s4[idx] = hR4[((b * T + j) * T + i) * D4 + c];
    }
    if (tid < D4) q_s4[tid] = qkv4[(b * T + i) * D4 + tid];
    __syncthreads();

    // ---- Phase B: scores_j = sum_d (q[d]+hL[b,i,j,d]) * (k[b,j,d]+hR[b,j,i,d])
    // 16 warps x 8 j each. hL streamed from HBM, k from L2, hR/q from SMEM.
    const float4* hL4b = (const float4*)hL + (size_t)(b * T + i) * T * D4;
#pragma unroll 2
    for (int jj = 0; jj < 8; jj++) {
        int j = w * 8 + jj;
        const float4* hl4 = hL4b + j * D4;
        const float4* k4  = qkv4 + (Bq * T + b * T + j) * D4;
        float acc = 0.f;
#pragma unroll
        for (int it = 0; it < 3; it++) {
            int c = lane + it * 32;
            if (c < D4) {
                float4 hl = hl4[c];
                float4 kk = k4[c];
                float4 hr = hR_s4[j * D4 + c];
                float4 qq = q_s4[c];
                acc += (qq.x + hl.x) * (kk.x + hr.x)
                     + (qq.y + hl.y) * (kk.y + hr.y)
                     + (qq.z + hl.z) * (kk.z + hr.z)
                     + (qq.w + hl.w) * (kk.w + hr.w);
            }
        }
#pragma unroll
        for (int o = 16; o > 0; o >>= 1)
            acc += __shfl_xor_sync(0xffffffffu, acc, o);
        if (lane == 0) scores_s[j] = acc;
    }
    __syncthreads();

    // ---- Phase C: p = softmax(scores); attn = softmax(1000*p) (clip no-op)
    // p_max = 1/sum exactly (max exp term is 1), so 1000*(p-p_max) = 1000*inv*(e-1)
    if (w == 0) {
        float s0 = scores_s[lane],      s1 = scores_s[lane + 32];
        float s2 = scores_s[lane + 64], s3 = scores_s[lane + 96];
        float m = fmaxf(fmaxf(s0, s1), fmaxf(s2, s3));
#pragma unroll
        for (int o = 16; o > 0; o >>= 1)
            m = fmaxf(m, __shfl_xor_sync(0xffffffffu, m, o));
        float e0 = expf(s0 - m), e1 = expf(s1 - m);
        float e2 = expf(s2 - m), e3 = expf(s3 - m);
        float sum = e0 + e1 + e2 + e3;
#pragma unroll
        for (int o = 16; o > 0; o >>= 1)
            sum += __shfl_xor_sync(0xffffffffu, sum, o);
        float inv = 1.f / sum;
        float a0 = expf(1000.f * inv * (e0 - 1.f));
        float a1 = expf(1000.f * inv * (e1 - 1.f));
        float a2 = expf(1000.f * inv * (e2 - 1.f));
        float a3 = expf(1000.f * inv * (e3 - 1.f));
        float sum2 = a0 + a1 + a2 + a3;
#pragma unroll
        for (int o = 16; o > 0; o >>= 1)
            sum2 += __shfl_xor_sync(0xffffffffu, sum2, o);
        float inv2 = 1.f / sum2;
        attn_s[lane]      = a0 * inv2;
        attn_s[lane + 32] = a1 * inv2;
        attn_s[lane + 64] = a2 * inv2;
        attn_s[lane + 96] = a3 * inv2;
    }
    __syncthreads();

    // ---- Phase D: out[b,i,d] = sum_j attn_j * (v[b,j,d] + hR_s[j][d])
    // attn is near-one-hot after sharpening: skip negligible j (saves L2).
    if (tid < D) {
        const float* vg  = g_qkv + (2 * Bq * T + b * T) * D + tid;
        const float* hrp = hR_s + tid;
        float acc = 0.f;
#pragma unroll 8
        for (int j = 0; j < T; j++) {
            float a = attn_s[j];
            if (a > 1e-12f)
                acc += a * (vg[j * D] + hrp[j * D]);
        }
        out[(b * T + i) * D + tid] = acc;
    }
}

// ---------------------------------------------------------------------------
extern "C" void kernel_launch(void* const* d_in, const int* in_sizes, int n_in,
                              void* d_out, int out_size)
{
    const float* query = (const float*)d_in[0];
    const float* key   = (const float*)d_in[1];
    const float* value = (const float*)d_in[2];
    const float* hL    = (const float*)d_in[3];
    const float* hR    = (const float*)d_in[4];
    const float* WQ    = (const float*)d_in[5];
    const float* bQ    = (const float*)d_in[6];
    const float* WK    = (const float*)d_in[7];
    const float* bK    = (const float*)d_in[8];
    float* out = (float*)d_out;

    cudaFuncSetAttribute(attn_kernel,
                         cudaFuncAttributeMaxDynamicSharedMemorySize,
                         SMEM_BYTES);

    // 1536 rows x 300 cols: 24 row tiles x 5 col tiles
    proj_kernel<<<dim3(5, 24), 256>>>(query, key, value, WQ, bQ, WK, bK);
    attn_kernel<<<Bq * T, 512, SMEM_BYTES>>>(hL, hR, out);
}

// round 2
// speedup vs baseline: 1.3450x; 1.3450x over previous
#include <cuda_runtime.h>

#define Bq 4
#define T 128
#define D 300
#define D4 75            // D / 4 (float4 count per row)

// Scratch for projected q (rows 0..511), k (512..1023), v (1024..1535)
__device__ __align__(16) float g_qkv[3 * Bq * T * D];

// ---------------------------------------------------------------------------
// Kernel 1: batched projection GEMM, double-buffered.
// out[r,c] = A[r,:] . W[c,:] + bias[c]   (torch nn.Linear semantics)
// rows 0..511 -> query/WQ/bQ, 512..1023 -> key/WK/bK, 1024..1535 -> value/WK/bK
// 64x64 tile, 256 threads, 4x4 microtile, k-chunk 32, fp32.
// ---------------------------------------------------------------------------
__global__ __launch_bounds__(256) void proj_kernel(
    const float* __restrict__ query, const float* __restrict__ key,
    const float* __restrict__ value,
    const float* __restrict__ WQ, const float* __restrict__ bQ,
    const float* __restrict__ WK, const float* __restrict__ bK)
{
    __shared__ float A_s[2][32][65];
    __shared__ float W_s[2][32][65];

    const int row0 = blockIdx.y * 64;
    const int col0 = blockIdx.x * 64;
    const int tid  = threadIdx.x;
    const int tx   = tid & 15;   // column micro-group
    const int ty   = tid >> 4;   // row micro-group

    const int sel = row0 >> 9;   // 0: query, 1: key, 2: value (tiles never straddle)
    const float* Ap = (sel == 0) ? query : (sel == 1 ? key : value);
    const float* Wp = (sel == 0) ? WQ : WK;
    const float* bp = (sel == 0) ? bQ : bK;
    const int arow0 = row0 & 511;

    // loader mapping: e (k within chunk) = tid&31, rows x = (tid>>5) + s*8
    const int le = tid & 31;
    const int lx = tid >> 5;

    float acc[4][4];
#pragma unroll
    for (int r = 0; r < 4; r++)
#pragma unroll
        for (int c = 0; c < 4; c++) acc[r][c] = 0.f;

    const int NC = (D + 31) / 32;   // 10 chunks
    float a_r[8], w_r[8];

    // prefetch chunk 0
    {
        int kk = le;                 // k0 = 0
#pragma unroll
        for (int s = 0; s < 8; s++) {
            int x = lx + s * 8;
            a_r[s] = Ap[(arow0 + x) * D + kk];
            int gc = col0 + x;
            w_r[s] = (gc < D) ? Wp[gc * D + kk] : 0.f;
        }
#pragma unroll
        for (int s = 0; s < 8; s++) {
            A_s[0][le][lx + s * 8] = a_r[s];
            W_s[0][le][lx + s * 8] = w_r[s];
        }
    }
    __syncthreads();

    for (int ch = 0; ch < NC; ch++) {
        const int buf = ch & 1;
        // prefetch next chunk into registers (overlaps compute)
        if (ch + 1 < NC) {
            int kk = (ch + 1) * 32 + le;
            bool kv = kk < D;
#pragma unroll
            for (int s = 0; s < 8; s++) {
                int x = lx + s * 8;
                a_r[s] = kv ? Ap[(arow0 + x) * D + kk] : 0.f;
                int gc = col0 + x;
                w_r[s] = (kv && gc < D) ? Wp[gc * D + kk] : 0.f;
            }
        }
        // compute on current buffer
#pragma unroll
        for (int e = 0; e < 32; e++) {
            float av[4], wv[4];
#pragma unroll
            for (int r = 0; r < 4; r++) av[r] = A_s[buf][e][ty * 4 + r];
#pragma unroll
            for (int c = 0; c < 4; c++) wv[c] = W_s[buf][e][tx * 4 + c];
#pragma unroll
            for (int r = 0; r < 4; r++)
#pragma unroll
                for (int c = 0; c < 4; c++) acc[r][c] += av[r] * wv[c];
        }
        // store prefetch into the other buffer (safe: its readers passed the
        // sync at the end of the previous iteration)
        if (ch + 1 < NC) {
#pragma unroll
            for (int s = 0; s < 8; s++) {
                A_s[1 - buf][le][lx + s * 8] = a_r[s];
                W_s[1 - buf][le][lx + s * 8] = w_r[s];
            }
        }
        __syncthreads();
    }

#pragma unroll
    for (int r = 0; r < 4; r++) {
        int gr = row0 + ty * 4 + r;
#pragma unroll
        for (int c = 0; c < 4; c++) {
            int gc = col0 + tx * 4 + c;
            if (gc < D) g_qkv[gr * D + gc] = acc[r][c] + bp[gc];
        }
    }
}

// ---------------------------------------------------------------------------
// Kernel 2: fused attention. One CTA per (b, i), 256 threads, ~2.3KB smem
// -> 3 CTAs/SM. hL and hR are streamed straight from HBM in the scoring
// loop (each element read exactly once chip-wide). Output pass re-reads
// v / hR only for the (near-one-hot) significant attention entries.
// ---------------------------------------------------------------------------
__global__ __launch_bounds__(256, 3) void attn_kernel(
    const float* __restrict__ hL, const float* __restrict__ hR,
    float* __restrict__ out)
{
    __shared__ float q_s[304];
    __shared__ float scores_s[128];
    __shared__ float attn_s[128];

    const int tid  = threadIdx.x;
    const int lane = tid & 31;
    const int w    = tid >> 5;           // 8 warps
    const int b    = blockIdx.x >> 7;
    const int i    = blockIdx.x & 127;

    const float4* qkv4 = (const float4*)g_qkv;

    // ---- load q_i (L2-hot, tiny) ----
    if (tid < D4) ((float4*)q_s)[tid] = qkv4[(b * T + i) * D4 + tid];
    __syncthreads();

    const float4* q4 = (const float4*)q_s;
    const float4  qa = q4[lane];
    const float4  qb = q4[lane + 32];
    const bool    has_c = (lane < D4 - 64);          // lane < 11
    const float4  qc = has_c ? q4[lane + 64] : make_float4(0.f, 0.f, 0.f, 0.f);

    // ---- scoring: scores_j = sum_d (q[d]+hL[b,i,j,d]) * (k[b,j,d]+hR[b,j,i,d])
    const float4* hL4 = (const float4*)hL + (size_t)(b * T + i) * T * D4;
    const float4* hRb = (const float4*)hR + ((size_t)b * T * T + i) * D4;
    const float4* k4b = qkv4 + (Bq * T + b * T) * D4;

#pragma unroll 2
    for (int jj = 0; jj < 16; jj++) {
        const int j = w * 16 + jj;
        const float4* hl = hL4 + j * D4;
        const float4* hr = hRb + (size_t)j * T * D4;
        const float4* kp = k4b + j * D4;

        float4 l0 = hl[lane],      r0 = hr[lane],      k0 = kp[lane];
        float4 l1 = hl[lane + 32], r1 = hr[lane + 32], k1 = kp[lane + 32];
        float4 l2, r2, k2;
        if (has_c) { l2 = hl[lane + 64]; r2 = hr[lane + 64]; k2 = kp[lane + 64]; }

        float acc = (qa.x + l0.x) * (k0.x + r0.x) + (qa.y + l0.y) * (k0.y + r0.y)
                  + (qa.z + l0.z) * (k0.z + r0.z) + (qa.w + l0.w) * (k0.w + r0.w)
                  + (qb.x + l1.x) * (k1.x + r1.x) + (qb.y + l1.y) * (k1.y + r1.y)
                  + (qb.z + l1.z) * (k1.z + r1.z) + (qb.w + l1.w) * (k1.w + r1.w);
        if (has_c) {
            acc += (qc.x + l2.x) * (k2.x + r2.x) + (qc.y + l2.y) * (k2.y + r2.y)
                 + (qc.z + l2.z) * (k2.z + r2.z) + (qc.w + l2.w) * (k2.w + r2.w);
        }
#pragma unroll
        for (int o = 16; o > 0; o >>= 1)
            acc += __shfl_xor_sync(0xffffffffu, acc, o);
        if (lane == 0) scores_s[j] = acc;
    }
    __syncthreads();

    // ---- p = softmax(scores); attn = softmax(1000*p); clip is a no-op.
    // p_max = 1/sum exactly (max exp term is 1): 1000*(p-p_max) = 1000*inv*(e-1)
    if (w == 0) {
        float s0 = scores_s[lane],      s1 = scores_s[lane + 32];
        float s2 = scores_s[lane + 64], s3 = scores_s[lane + 96];
        float m = fmaxf(fmaxf(s0, s1), fmaxf(s2, s3));
#pragma unroll
        for (int o = 16; o > 0; o >>= 1)
            m = fmaxf(m, __shfl_xor_sync(0xffffffffu, m, o));
        float e0 = expf(s0 - m), e1 = expf(s1 - m);
        float e2 = expf(s2 - m), e3 = expf(s3 - m);
        float sum = e0 + e1 + e2 + e3;
#pragma unroll
        for (int o = 16; o > 0; o >>= 1)
            sum += __shfl_xor_sync(0xffffffffu, sum, o);
        float inv = 1.f / sum;
        float a0 = expf(1000.f * inv * (e0 - 1.f));
        float a1 = expf(1000.f * inv * (e1 - 1.f));
        float a2 = expf(1000.f * inv * (e2 - 1.f));
        float a3 = expf(1000.f * inv * (e3 - 1.f));
        float sum2 = a0 + a1 + a2 + a3;
#pragma unroll
        for (int o = 16; o > 0; o >>= 1)
            sum2 += __shfl_xor_sync(0xffffffffu, sum2, o);
        float inv2 = 1.f / sum2;
        attn_s[lane]      = a0 * inv2;
        attn_s[lane + 32] = a1 * inv2;
        attn_s[lane + 64] = a2 * inv2;
        attn_s[lane + 96] = a3 * inv2;
    }
    __syncthreads();

    // ---- output: out[b,i,d] = sum_j attn_j * (v[b,j,d] + hR[b,j,i,d])
    // attn is near-one-hot after x1000 sharpening: skip negligible j.
    const float* vg  = g_qkv + (size_t)(2 * Bq * T + b * T) * D;
    const float* hRs = hR + ((size_t)b * T * T + i) * D;
#pragma unroll
    for (int rep = 0; rep < 2; rep++) {
        int d = tid + rep * 256;
        if (d < D) {
            float acc = 0.f;
            for (int j = 0; j < T; j++) {
                float a = attn_s[j];
                if (a > 1e-12f)
                    acc += a * (vg[j * D + d] + hRs[(size_t)j * T * D + d]);
            }
            out[(b * T + i) * D + d] = acc;
        }
    }
}

// ---------------------------------------------------------------------------
extern "C" void kernel_launch(void* const* d_in, const int* in_sizes, int n_in,
                              void* d_out, int out_size)
{
    const float* query = (const float*)d_in[0];
    const float* key   = (const float*)d_in[1];
    const float* value = (const float*)d_in[2];
    const float* hL    = (const float*)d_in[3];
    const float* hR    = (const float*)d_in[4];
    const float* WQ    = (const float*)d_in[5];
    const float* bQ    = (const float*)d_in[6];
    const float* WK    = (const float*)d_in[7];
    const float* bK    = (const float*)d_in[8];
    float* out = (float*)d_out;

    // 1536 rows x 300 cols: 24 row tiles x 5 col tiles
    proj_kernel<<<dim3(5, 24), 256>>>(query, key, value, WQ, bQ, WK, bK);
    attn_kernel<<<Bq * T, 256>>>(hL, hR, out);
}

// round 4
// speedup vs baseline: 1.6219x; 1.2059x over previous
#include <cuda_runtime.h>

#define Bq 4
#define T 128
#define D 300
#define D4 75            // D / 4 (float4 count per row)

// Scratch for projected q (rows 0..511), k (512..1023), v (1024..1535)
__device__ __align__(16) float g_qkv[3 * Bq * T * D];

// ---------------------------------------------------------------------------
// Kernel 1: batched projection GEMM, 32x32 tiles (480 CTAs -> fills the chip),
// double-buffered k-chunks of 32.
// out[r,c] = A[r,:] . W[c,:] + bias[c]
// rows 0..511 -> query/WQ/bQ, 512..1023 -> key/WK/bK, 1024..1535 -> value/WK/bK
// SMEM row stride 34 (EVEN) so float2 reads at [e][2*t] stay 8B-aligned.
// ---------------------------------------------------------------------------
__global__ __launch_bounds__(256) void proj_kernel(
    const float* __restrict__ query, const float* __restrict__ key,
    const float* __restrict__ value,
    const float* __restrict__ WQ, const float* __restrict__ bQ,
    const float* __restrict__ WK, const float* __restrict__ bK)
{
    __shared__ float A_s[2][32][34];
    __shared__ float W_s[2][32][34];

    const int row0 = blockIdx.y * 32;
    const int col0 = blockIdx.x * 32;
    const int tid  = threadIdx.x;
    const int tx   = tid & 15;    // column micro-group (2 cols)
    const int ty   = tid >> 4;    // row micro-group (2 rows)

    const int sel = row0 >> 9;    // 0: query, 1: key, 2: value
    const float* Ap = (sel == 0) ? query : (sel == 1 ? key : value);
    const float* Wp = (sel == 0) ? WQ : WK;
    const float* bp = (sel == 0) ? bQ : bK;
    const int arow0 = row0 & 511;

    // loader mapping: each thread loads one float4 along k
    const int lm = tid >> 3;          // 0..31 (row within tile)
    const int lk = (tid & 7) * 4;     // 0,4,..,28 (k within chunk)
    const int gc = col0 + lm;         // W row (output col)
    const bool gcv = gc < D;

    float acc[2][2] = {{0.f, 0.f}, {0.f, 0.f}};

    const int NC = (D + 31) / 32;     // 10 chunks
    float4 a_r, w_r;

    // prefetch chunk 0 (always fully in-bounds: k 0..31 < 300)
    a_r = *(const float4*)&Ap[(arow0 + lm) * D + lk];
    w_r = gcv ? *(const float4*)&Wp[gc * D + lk] : make_float4(0.f, 0.f, 0.f, 0.f);
    A_s[0][lk + 0][lm] = a_r.x; A_s[0][lk + 1][lm] = a_r.y;
    A_s[0][lk + 2][lm] = a_r.z; A_s[0][lk + 3][lm] = a_r.w;
    W_s[0][lk + 0][lm] = w_r.x; W_s[0][lk + 1][lm] = w_r.y;
    W_s[0][lk + 2][lm] = w_r.z; W_s[0][lk + 3][lm] = w_r.w;
    __syncthreads();

    for (int ch = 0; ch < NC; ch++) {
        const int buf = ch & 1;
        if (ch + 1 < NC) {
            int kk = (ch + 1) * 32 + lk;
            bool kv = (kk + 3) < D;      // D % 4 == 0, so float4 never straddles
            a_r = kv ? *(const float4*)&Ap[(arow0 + lm) * D + kk]
                     : make_float4(0.f, 0.f, 0.f, 0.f);
            w_r = (kv && gcv) ? *(const float4*)&Wp[gc * D + kk]
                              : make_float4(0.f, 0.f, 0.f, 0.f);
        }
#pragma unroll
        for (int e = 0; e < 32; e++) {
            float2 av = *(const float2*)&A_s[buf][e][ty * 2];
            float2 wv = *(const float2*)&W_s[buf][e][tx * 2];
            acc[0][0] += av.x * wv.x;
            acc[0][1] += av.x * wv.y;
            acc[1][0] += av.y * wv.x;
            acc[1][1] += av.y * wv.y;
        }
        if (ch + 1 < NC) {
            A_s[1 - buf][lk + 0][lm] = a_r.x; A_s[1 - buf][lk + 1][lm] = a_r.y;
            A_s[1 - buf][lk + 2][lm] = a_r.z; A_s[1 - buf][lk + 3][lm] = a_r.w;
            W_s[1 - buf][lk + 0][lm] = w_r.x; W_s[1 - buf][lk + 1][lm] = w_r.y;
            W_s[1 - buf][lk + 2][lm] = w_r.z; W_s[1 - buf][lk + 3][lm] = w_r.w;
        }
        __syncthreads();
    }

#pragma unroll
    for (int r = 0; r < 2; r++) {
        int gr = row0 + ty * 2 + r;
#pragma unroll
        for (int c = 0; c < 2; c++) {
            int gcol = col0 + tx * 2 + c;
            if (gcol < D) g_qkv[gr * D + gcol] = acc[r][c] + bp[gcol];
        }
    }
}

// ---------------------------------------------------------------------------
// Kernel 2: fused attention. One CTA per (b, i), 256 threads, 4 CTAs/SM
// (592 slots >= 512 CTAs => SINGLE WAVE). hL / hR / k streamed straight
// from HBM in the scoring loop; q read from SMEM to keep regs <= 64.
// ---------------------------------------------------------------------------
__global__ __launch_bounds__(256, 4) void attn_kernel(
    const float* __restrict__ hL, const float* __restrict__ hR,
    float* __restrict__ out)
{
    __shared__ float q_s[304];
    __shared__ float scores_s[128];
    __shared__ float attn_s[128];

    const int tid  = threadIdx.x;
    const int lane = tid & 31;
    const int w    = tid >> 5;           // 8 warps
    const int b    = blockIdx.x >> 7;
    const int i    = blockIdx.x & 127;

    const float4* qkv4 = (const float4*)g_qkv;

    // ---- load q_i (L2-hot, tiny) ----
    if (tid < D4) ((float4*)q_s)[tid] = qkv4[(b * T + i) * D4 + tid];
    __syncthreads();

    const float4* q4 = (const float4*)q_s;
    const bool has_c = (lane < D4 - 64);           // lane < 11

    // ---- scoring: scores_j = sum_d (q[d]+hL[b,i,j,d]) * (k[b,j,d]+hR[b,j,i,d])
    const float4* hL4 = (const float4*)hL + (size_t)(b * T + i) * T * D4;
    const float4* hRb = (const float4*)hR + ((size_t)b * T * T + i) * D4;
    const float4* k4b = qkv4 + (Bq * T + b * T) * D4;

#pragma unroll 2
    for (int jj = 0; jj < 16; jj++) {
        const int j = w * 16 + jj;
        const float4* hl = hL4 + j * D4;
        const float4* hr = hRb + (size_t)j * T * D4;
        const float4* kp = k4b + j * D4;

        float4 l0 = hl[lane],      r0 = hr[lane],      k0 = kp[lane];
        float4 l1 = hl[lane + 32], r1 = hr[lane + 32], k1 = kp[lane + 32];
        float4 l2, r2, k2;
        if (has_c) { l2 = hl[lane + 64]; r2 = hr[lane + 64]; k2 = kp[lane + 64]; }

        float4 qa = q4[lane];
        float acc = (qa.x + l0.x) * (k0.x + r0.x) + (qa.y + l0.y) * (k0.y + r0.y)
                  + (qa.z + l0.z) * (k0.z + r0.z) + (qa.w + l0.w) * (k0.w + r0.w);
        float4 qb = q4[lane + 32];
        acc += (qb.x + l1.x) * (k1.x + r1.x) + (qb.y + l1.y) * (k1.y + r1.y)
             + (qb.z + l1.z) * (k1.z + r1.z) + (qb.w + l1.w) * (k1.w + r1.w);
        if (has_c) {
            float4 qc = q4[lane + 64];
            acc += (qc.x + l2.x) * (k2.x + r2.x) + (qc.y + l2.y) * (k2.y + r2.y)
                 + (qc.z + l2.z) * (k2.z + r2.z) + (qc.w + l2.w) * (k2.w + r2.w);
        }
#pragma unroll
        for (int o = 16; o > 0; o >>= 1)
            acc += __shfl_xor_sync(0xffffffffu, acc, o);
        if (lane == 0) scores_s[j] = acc;
    }
    __syncthreads();

    // ---- p = softmax(scores); attn = softmax(1000*p); clip is a no-op.
    // p_max = 1/sum exactly (max exp term is 1): 1000*(p-p_max) = 1000*inv*(e-1)
    if (w == 0) {
        float s0 = scores_s[lane],      s1 = scores_s[lane + 32];
        float s2 = scores_s[lane + 64], s3 = scores_s[lane + 96];
        float m = fmaxf(fmaxf(s0, s1), fmaxf(s2, s3));
#pragma unroll
        for (int o = 16; o > 0; o >>= 1)
            m = fmaxf(m, __shfl_xor_sync(0xffffffffu, m, o));
        float e0 = expf(s0 - m), e1 = expf(s1 - m);
        float e2 = expf(s2 - m), e3 = expf(s3 - m);
        float sum = e0 + e1 + e2 + e3;
#pragma unroll
        for (int o = 16; o > 0; o >>= 1)
            sum += __shfl_xor_sync(0xffffffffu, sum, o);
        float inv = 1.f / sum;
        float a0 = expf(1000.f * inv * (e0 - 1.f));
        float a1 = expf(1000.f * inv * (e1 - 1.f));
        float a2 = expf(1000.f * inv * (e2 - 1.f));
        float a3 = expf(1000.f * inv * (e3 - 1.f));
        float sum2 = a0 + a1 + a2 + a3;
#pragma unroll
        for (int o = 16; o > 0; o >>= 1)
            sum2 += __shfl_xor_sync(0xffffffffu, sum2, o);
        float inv2 = 1.f / sum2;
        attn_s[lane]      = a0 * inv2;
        attn_s[lane + 32] = a1 * inv2;
        attn_s[lane + 64] = a2 * inv2;
        attn_s[lane + 96] = a3 * inv2;
    }
    __syncthreads();

    // ---- output: out[b,i,d] = sum_j attn_j * (v[b,j,d] + hR[b,j,i,d])
    // attn is near-one-hot after x1000 sharpening: skip negligible j.
    const float* vg  = g_qkv + (size_t)(2 * Bq * T + b * T) * D;
    const float* hRs = hR + ((size_t)b * T * T + i) * D;
#pragma unroll
    for (int rep = 0; rep < 2; rep++) {
        int d = tid + rep * 256;
        if (d < D) {
            float acc = 0.f;
            for (int j = 0; j < T; j++) {
                float a = attn_s[j];
                if (a > 1e-12f)
                    acc += a * (vg[j * D + d] + hRs[(size_t)j * T * D + d]);
            }
            out[(b * T + i) * D + d] = acc;
        }
    }
}

// ---------------------------------------------------------------------------
extern "C" void kernel_launch(void* const* d_in, const int* in_sizes, int n_in,
                              void* d_out, int out_size)
{
    const float* query = (const float*)d_in[0];
    const float* key   = (const float*)d_in[1];
    const float* value = (const float*)d_in[2];
    const float* hL    = (const float*)d_in[3];
    const float* hR    = (const float*)d_in[4];
    const float* WQ    = (const float*)d_in[5];
    const float* bQ    = (const float*)d_in[6];
    const float* WK    = (const float*)d_in[7];
    const float* bK    = (const float*)d_in[8];
    float* out = (float*)d_out;

    // 1536 rows x 300 cols: 48 row tiles x 10 col tiles = 480 CTAs
    proj_kernel<<<dim3(10, 48), 256>>>(query, key, value, WQ, bQ, WK, bK);
    attn_kernel<<<Bq * T, 256>>>(hL, hR, out);
}

// round 5
// speedup vs baseline: 1.7884x; 1.1026x over previous
#include <cuda_runtime.h>

#define Bq 4
#define T 128
#define D 300
#define D4 75            // D / 4 (float4 count per row)

// Scratch for projected q (rows 0..511), k (512..1023), v (1024..1535)
__device__ __align__(16) float g_qkv[3 * Bq * T * D];

// ---------------------------------------------------------------------------
// Kernel 1: batched projection GEMM.
// 32x64 tiles, 128 threads, 4x4 microtile (16 FMA per 32B LDS), k-chunk 32,
// double-buffered. Grid 5 x 48 = 240 CTAs.
// out[r,c] = A[r,:] . W[c,:] + bias[c]
// rows 0..511 -> query/WQ/bQ, 512..1023 -> key/WK/bK, 1024..1535 -> value/WK/bK
// ---------------------------------------------------------------------------
__global__ __launch_bounds__(128) void proj_kernel(
    const float* __restrict__ query, const float* __restrict__ key,
    const float* __restrict__ value,
    const float* __restrict__ WQ, const float* __restrict__ bQ,
    const float* __restrict__ WK, const float* __restrict__ bK)
{
    __shared__ float A_s[2][32][36];   // [k-in-chunk][row]  (144B rows, 16B-aligned)
    __shared__ float W_s[2][32][68];   // [k-in-chunk][col]  (272B rows, 16B-aligned)

    const int row0 = blockIdx.y * 32;
    const int col0 = blockIdx.x * 64;
    const int tid  = threadIdx.x;
    const int tx   = tid & 15;    // 16 col groups x 4 cols = 64
    const int ty   = tid >> 4;    // 8 row groups x 4 rows = 32

    const int sel = row0 >> 9;    // 0: query, 1: key, 2: value (tiles never straddle)
    const float* Ap = (sel == 0) ? query : (sel == 1 ? key : value);
    const float* Wp = (sel == 0) ? WQ : WK;
    const float* bp = (sel == 0) ? bQ : bK;
    const int arow0 = row0 & 511;

    const int NC = (D + 31) / 32;     // 10 chunks (chunk 9 partial: k 288..299)
    float4 a_r[2], w_r[4];

    // loader maps (float4 along k)
    //   A: idx = p*128+tid (p<2): arow = idx&31, ak = (idx>>5)*4
    //   W: idx = p*128+tid (p<4): wrow = idx&63, wk = (idx>>6)*4
    auto fetch = [&](int k0) {
#pragma unroll
        for (int p = 0; p < 2; p++) {
            int idx = p * 128 + tid;
            int ar = idx & 31, kk = k0 + ((idx >> 5) << 2);
            a_r[p] = (kk < D) ? *(const float4*)&Ap[(arow0 + ar) * D + kk]
                              : make_float4(0.f, 0.f, 0.f, 0.f);
        }
#pragma unroll
        for (int p = 0; p < 4; p++) {
            int idx = p * 128 + tid;
            int wr = idx & 63, kk = k0 + ((idx >> 6) << 2);
            int gc = col0 + wr;
            w_r[p] = (kk < D && gc < D) ? *(const float4*)&Wp[gc * D + kk]
                                        : make_float4(0.f, 0.f, 0.f, 0.f);
        }
    };
    auto store = [&](int buf) {
#pragma unroll
        for (int p = 0; p < 2; p++) {
            int idx = p * 128 + tid;
            int ar = idx & 31, e = (idx >> 5) << 2;
            A_s[buf][e + 0][ar] = a_r[p].x; A_s[buf][e + 1][ar] = a_r[p].y;
            A_s[buf][e + 2][ar] = a_r[p].z; A_s[buf][e + 3][ar] = a_r[p].w;
        }
#pragma unroll
        for (int p = 0; p < 4; p++) {
            int idx = p * 128 + tid;
            int wr = idx & 63, e = (idx >> 6) << 2;
            W_s[buf][e + 0][wr] = w_r[p].x; W_s[buf][e + 1][wr] = w_r[p].y;
            W_s[buf][e + 2][wr] = w_r[p].z; W_s[buf][e + 3][wr] = w_r[p].w;
        }
    };

    float acc[4][4];
#pragma unroll
    for (int r = 0; r < 4; r++)
#pragma unroll
        for (int c = 0; c < 4; c++) acc[r][c] = 0.f;

    fetch(0);
    store(0);
    __syncthreads();

    for (int ch = 0; ch < NC; ch++) {
        const int buf = ch & 1;
        if (ch + 1 < NC) fetch((ch + 1) * 32);
#pragma unroll
        for (int e = 0; e < 32; e++) {
            float4 av = *(const float4*)&A_s[buf][e][ty * 4];
            float4 wv = *(const float4*)&W_s[buf][e][tx * 4];
            float a4[4] = {av.x, av.y, av.z, av.w};
            float w4[4] = {wv.x, wv.y, wv.z, wv.w};
#pragma unroll
            for (int r = 0; r < 4; r++)
#pragma unroll
                for (int c = 0; c < 4; c++) acc[r][c] += a4[r] * w4[c];
        }
        if (ch + 1 < NC) store(1 - buf);
        __syncthreads();
    }

#pragma unroll
    for (int r = 0; r < 4; r++) {
        int gr = row0 + ty * 4 + r;
#pragma unroll
        for (int c = 0; c < 4; c++) {
            int gcol = col0 + tx * 4 + c;
            if (gcol < D) g_qkv[gr * D + gcol] = acc[r][c] + bp[gcol];
        }
    }
}

// ---------------------------------------------------------------------------
// Kernel 2: fused attention. One CTA per (b, i), 256 threads, 4 CTAs/SM
// (single wave). Scoring loop is a pure LDG/FMA stream — per-lane partials
// go to SMEM and are reduced in one bulk pass (no shuffle chains in-loop).
// ---------------------------------------------------------------------------
__global__ __launch_bounds__(256, 4) void attn_kernel(
    const float* __restrict__ hL, const float* __restrict__ hR,
    float* __restrict__ out)
{
    __shared__ float partial_s[128][36];   // [j][lane], 16B-aligned row stride
    __shared__ float q_s[304];
    __shared__ float scores_s[128];
    __shared__ float attn_s[128];

    const int tid  = threadIdx.x;
    const int lane = tid & 31;
    const int w    = tid >> 5;           // 8 warps
    const int b    = blockIdx.x >> 7;
    const int i    = blockIdx.x & 127;

    const float4* qkv4 = (const float4*)g_qkv;

    // ---- load q_i (L2-hot, tiny) ----
    if (tid < D4) ((float4*)q_s)[tid] = qkv4[(b * T + i) * D4 + tid];
    __syncthreads();

    const float4* q4 = (const float4*)q_s;
    const bool has_c = (lane < D4 - 64);           // lane < 11

    // ---- scoring stream: partial[j][lane] = sum over this lane's d-slice of
    //      (q[d]+hL[b,i,j,d]) * (k[b,j,d]+hR[b,j,i,d])
    const float4* hL4 = (const float4*)hL + (size_t)(b * T + i) * T * D4;
    const float4* hRb = (const float4*)hR + ((size_t)b * T * T + i) * D4;
    const float4* k4b = qkv4 + (Bq * T + b * T) * D4;

#pragma unroll 2
    for (int jj = 0; jj < 16; jj++) {
        const int j = w * 16 + jj;
        const float4* hl = hL4 + j * D4;
        const float4* hr = hRb + (size_t)j * T * D4;
        const float4* kp = k4b + j * D4;

        float4 l0 = hl[lane],      r0 = hr[lane],      k0 = kp[lane];
        float4 l1 = hl[lane + 32], r1 = hr[lane + 32], k1 = kp[lane + 32];
        float4 l2, r2, k2;
        if (has_c) { l2 = hl[lane + 64]; r2 = hr[lane + 64]; k2 = kp[lane + 64]; }

        float4 qa = q4[lane];
        float acc = (qa.x + l0.x) * (k0.x + r0.x) + (qa.y + l0.y) * (k0.y + r0.y)
                  + (qa.z + l0.z) * (k0.z + r0.z) + (qa.w + l0.w) * (k0.w + r0.w);
        float4 qb = q4[lane + 32];
        acc += (qb.x + l1.x) * (k1.x + r1.x) + (qb.y + l1.y) * (k1.y + r1.y)
             + (qb.z + l1.z) * (k1.z + r1.z) + (qb.w + l1.w) * (k1.w + r1.w);
        if (has_c) {
            float4 qc = q4[lane + 64];
            acc += (qc.x + l2.x) * (k2.x + r2.x) + (qc.y + l2.y) * (k2.y + r2.y)
                 + (qc.z + l2.z) * (k2.z + r2.z) + (qc.w + l2.w) * (k2.w + r2.w);
        }
        partial_s[j][lane] = acc;
    }
    __syncthreads();

    // ---- bulk reduction: scores[j] = sum of 32 lane partials ----
    if (tid < 128) {
        const float4* row = (const float4*)partial_s[tid];
        float4 s0 = row[0], s1 = row[1], s2 = row[2], s3 = row[3];
        float4 s4 = row[4], s5 = row[5], s6 = row[6], s7 = row[7];
        float sum = ((s0.x + s0.y) + (s0.z + s0.w)) + ((s1.x + s1.y) + (s1.z + s1.w))
                  + ((s2.x + s2.y) + (s2.z + s2.w)) + ((s3.x + s3.y) + (s3.z + s3.w))
                  + ((s4.x + s4.y) + (s4.z + s4.w)) + ((s5.x + s5.y) + (s5.z + s5.w))
                  + ((s6.x + s6.y) + (s6.z + s6.w)) + ((s7.x + s7.y) + (s7.z + s7.w));
        scores_s[tid] = sum;
    }
    __syncthreads();

    // ---- p = softmax(scores); attn = softmax(1000*p); clip is a no-op.
    // p_max = 1/sum exactly (max exp term is 1): 1000*(p-p_max) = 1000*inv*(e-1)
    if (w == 0) {
        float s0 = scores_s[lane],      s1 = scores_s[lane + 32];
        float s2 = scores_s[lane + 64], s3 = scores_s[lane + 96];
        float m = fmaxf(fmaxf(s0, s1), fmaxf(s2, s3));
#pragma unroll
        for (int o = 16; o > 0; o >>= 1)
            m = fmaxf(m, __shfl_xor_sync(0xffffffffu, m, o));
        float e0 = expf(s0 - m), e1 = expf(s1 - m);
        float e2 = expf(s2 - m), e3 = expf(s3 - m);
        float sum = e0 + e1 + e2 + e3;
#pragma unroll
        for (int o = 16; o > 0; o >>= 1)
            sum += __shfl_xor_sync(0xffffffffu, sum, o);
        float inv = 1.f / sum;
        float a0 = expf(1000.f * inv * (e0 - 1.f));
        float a1 = expf(1000.f * inv * (e1 - 1.f));
        float a2 = expf(1000.f * inv * (e2 - 1.f));
        float a3 = expf(1000.f * inv * (e3 - 1.f));
        float sum2 = a0 + a1 + a2 + a3;
#pragma unroll
        for (int o = 16; o > 0; o >>= 1)
            sum2 += __shfl_xor_sync(0xffffffffu, sum2, o);
        float inv2 = 1.f / sum2;
        attn_s[lane]      = a0 * inv2;
        attn_s[lane + 32] = a1 * inv2;
        attn_s[lane + 64] = a2 * inv2;
        attn_s[lane + 96] = a3 * inv2;
    }
    __syncthreads();

    // ---- output: out[b,i,d] = sum_j attn_j * (v[b,j,d] + hR[b,j,i,d])
    // attn is near-one-hot after x1000 sharpening: skip negligible j.
    const float* vg  = g_qkv + (size_t)(2 * Bq * T + b * T) * D;
    const float* hRs = hR + ((size_t)b * T * T + i) * D;
#pragma unroll
    for (int rep = 0; rep < 2; rep++) {
        int d = tid + rep * 256;
        if (d < D) {
            float acc = 0.f;
            for (int j = 0; j < T; j++) {
                float a = attn_s[j];
                if (a > 1e-12f)
                    acc += a * (vg[j * D + d] + hRs[(size_t)j * T * D + d]);
            }
            out[(b * T + i) * D + d] = acc;
        }
    }
}

// ---------------------------------------------------------------------------
extern "C" void kernel_launch(void* const* d_in, const int* in_sizes, int n_in,
                              void* d_out, int out_size)
{
    const float* query = (const float*)d_in[0];
    const float* key   = (const float*)d_in[1];
    const float* value = (const float*)d_in[2];
    const float* hL    = (const float*)d_in[3];
    const float* hR    = (const float*)d_in[4];
    const float* WQ    = (const float*)d_in[5];
    const float* bQ    = (const float*)d_in[6];
    const float* WK    = (const float*)d_in[7];
    const float* bK    = (const float*)d_in[8];
    float* out = (float*)d_out;

    // 1536 rows x 300 cols: 48 row tiles x (5 x 64) col tiles = 240 CTAs
    proj_kernel<<<dim3(5, 48), 128>>>(query, key, value, WQ, bQ, WK, bK);
    attn_kernel<<<Bq * T, 256>>>(hL, hR, out);
}